// round 5
// baseline (speedup 1.0000x reference)
#include <cuda_runtime.h>
#include <math.h>

// Problem constants (fixed by the dataset)
#define B_   8
#define V_   25000
#define F_   20000
#define TPB  256
#define TILE 256
#define ROWSTRIDE 20   // per-face scalar row in smem (17 used, padded)
#define OUTC 1056

// Per-batch precomputed data (allocation-free scratch)
__device__ float g_incn[B_][4];       // normalized incidence vector
__device__ float g_emangle[B_][192];  // e_emangle = inc @ W_emangle + b (per-batch const)
__device__ float g_emfreq[B_][16];    // e_emfreq  = freq_log * W_emfreq + b (per-batch const)

__global__ void mc_precompute(const float* __restrict__ theta,
                              const float* __restrict__ phi,
                              const float* __restrict__ freq,
                              const float* __restrict__ W_emangle,
                              const float* __restrict__ b_emangle,
                              const float* __restrict__ W_emfreq,
                              const float* __restrict__ b_emfreq) {
    const float D2R = 0.017453292519943295f;
    int tid = threadIdx.x;
    if (tid < B_) {
        float th = theta[tid] * D2R, ph = phi[tid] * D2R;
        float ix = sinf(ph) * cosf(th);
        float iy = sinf(ph) * sinf(th);
        float iz = cosf(ph);
        float n  = sqrtf(ix*ix + iy*iy + iz*iz);
        float inv = 1.0f / fmaxf(n, 1e-12f);
        g_incn[tid][0] = ix * inv;
        g_incn[tid][1] = iy * inv;
        g_incn[tid][2] = iz * inv;
        g_incn[tid][3] = 0.0f;
    }
    for (int idx = tid; idx < B_ * 208; idx += blockDim.x) {
        int b = idx / 208, r = idx % 208;
        float th = theta[b] * D2R, ph = phi[b] * D2R;
        float ix = sinf(ph) * cosf(th);
        float iy = sinf(ph) * sinf(th);
        float iz = cosf(ph);
        if (r < 192) {
            g_emangle[b][r] = ix * W_emangle[r]
                            + iy * W_emangle[192 + r]
                            + iz * W_emangle[384 + r]
                            + b_emangle[r];
        } else {
            int j = r - 192;
            float fl = (log10f(freq[b]) + 1.0f) * 0.5f;  // (log10(f)-log10(0.1))/(log10(10)-log10(0.1))
            g_emfreq[b][j] = fl * W_emfreq[j] + b_emfreq[j];
        }
    }
}

// Column segments of the 1056-wide output:
//   [0,576)    e_coor    (9 inputs: face coords)
//   [576,624)  e_angle   (3 inputs: angles)
//   [624,816)  e_normal  (3 inputs: normal)
//   [816,832)  e_area    (1 input: area)
//   [832,1024) e_emangle (per-batch constant)
//   [1024,1040) e_emnoangle (1 input)
//   [1040,1056) e_emfreq  (per-batch constant)
__global__ void __launch_bounds__(TPB, 2)
mc_encode(const float* __restrict__ vertices,
          const int*   __restrict__ faces,
          const float* __restrict__ W_angle,     const float* __restrict__ b_angle,
          const float* __restrict__ W_area,      const float* __restrict__ b_area,
          const float* __restrict__ W_normal,    const float* __restrict__ b_normal,
          const float* __restrict__ W_emnoangle, const float* __restrict__ b_emnoangle,
          const float* __restrict__ W_coor,      const float* __restrict__ b_coor,
          float* __restrict__ out) {
    __shared__ float sh[TILE * ROWSTRIDE];
    const int t     = threadIdx.x;
    const int b     = blockIdx.y;
    const int fbase = blockIdx.x * TILE;
    const int c0    = 4 * t;

    // ---- load this thread's column-group weights into registers (once per block) ----
    float w[36];
    float4 bias;
    int seg;
    if (c0 < 576) {
        seg = 0;
        #pragma unroll
        for (int i = 0; i < 9; i++)
            *(float4*)&w[4*i] = *(const float4*)&W_coor[i*576 + c0];
        bias = *(const float4*)&b_coor[c0];
    } else if (c0 < 624) {
        seg = 1; int j = c0 - 576;
        #pragma unroll
        for (int i = 0; i < 3; i++)
            *(float4*)&w[4*i] = *(const float4*)&W_angle[i*48 + j];
        bias = *(const float4*)&b_angle[j];
    } else if (c0 < 816) {
        seg = 2; int j = c0 - 624;
        #pragma unroll
        for (int i = 0; i < 3; i++)
            *(float4*)&w[4*i] = *(const float4*)&W_normal[i*192 + j];
        bias = *(const float4*)&b_normal[j];
    } else if (c0 < 832) {
        seg = 3; int j = c0 - 816;
        *(float4*)&w[0] = *(const float4*)&W_area[j];
        bias = *(const float4*)&b_area[j];
    } else {
        seg = 4; int j = c0 - 832;        // c0 in [832,1024): per-batch constant
        bias = *(const float4*)&g_emangle[b][j];
    }

    // tail group for threads 0..7: columns 1024+4t
    float  w2x = 0.f, w2y = 0.f, w2z = 0.f, w2w = 0.f;
    float4 bias2 = make_float4(0.f, 0.f, 0.f, 0.f);
    if (t < 4) {                          // e_emnoangle
        int j = 4 * t;
        w2x = W_emnoangle[j];   w2y = W_emnoangle[j+1];
        w2z = W_emnoangle[j+2]; w2w = W_emnoangle[j+3];
        bias2 = *(const float4*)&b_emnoangle[j];
    } else if (t < 8) {                   // e_emfreq (constant)
        int j = 4 * (t - 4);
        bias2 = *(const float4*)&g_emfreq[b][j];
    }

    const float inc0 = g_incn[b][0], inc1 = g_incn[b][1], inc2 = g_incn[b][2];

    // ---- Stage A: per-face geometry into shared memory ----
    const int f = fbase + t;
    if (f < F_) {
        const int* fp = faces + ((size_t)b * F_ + f) * 3;
        int i0 = fp[0], i1 = fp[1], i2 = fp[2];
        const float* vb = vertices + (size_t)b * V_ * 3;
        float v0x = vb[3*i0], v0y = vb[3*i0+1], v0z = vb[3*i0+2];
        float v1x = vb[3*i1], v1y = vb[3*i1+1], v1z = vb[3*i1+2];
        float v2x = vb[3*i2], v2y = vb[3*i2+1], v2z = vb[3*i2+2];
        // edges: face_coords - shifted, shifted = [v2, v0, v1]
        float e0x = v0x - v2x, e0y = v0y - v2y, e0z = v0z - v2z;
        float e1x = v1x - v0x, e1y = v1y - v0y, e1z = v1z - v0z;
        float e2x = v2x - v1x, e2y = v2y - v1y, e2z = v2z - v1z;
        float r0 = 1.0f / fmaxf(sqrtf(e0x*e0x + e0y*e0y + e0z*e0z), 1e-12f);
        float r1 = 1.0f / fmaxf(sqrtf(e1x*e1x + e1y*e1y + e1z*e1z), 1e-12f);
        float r2 = 1.0f / fmaxf(sqrtf(e2x*e2x + e2y*e2y + e2z*e2z), 1e-12f);
        float a0x = e0x*r0, a0y = e0y*r0, a0z = e0z*r0;
        float a1x = e1x*r1, a1y = e1y*r1, a1z = e1z*r1;
        float a2x = e2x*r2, a2y = e2y*r2, a2z = e2z*r2;
        const float LO = -1.0f + 1e-5f, HI = 1.0f - 1e-5f;
        // nd[j] = -sum_k nv[k][j] * nv[k][(j+2)%3]  (roll over coord axis)
        float nd0 = -(a0x*a0z + a1x*a1z + a2x*a2z);
        float nd1 = -(a0y*a0x + a1y*a1x + a2y*a2x);
        float nd2 = -(a0z*a0y + a1z*a1y + a2z*a2y);
        float ang0 = acosf(fminf(fmaxf(nd0, LO), HI));
        float ang1 = acosf(fminf(fmaxf(nd1, LO), HI));
        float ang2 = acosf(fminf(fmaxf(nd2, LO), HI));
        // crossed = cross(edge0, edge1)
        float cx = e0y*e1z - e0z*e1y;
        float cy = e0z*e1x - e0x*e1z;
        float cz = e0x*e1y - e0y*e1x;
        float cn = sqrtf(cx*cx + cy*cy + cz*cz);
        float rc = 1.0f / fmaxf(cn, 1e-12f);
        float nx = cx*rc, ny = cy*rc, nz = cz*rc;
        float area = 0.5f * cn;
        float dd = -(nx*inc0 + ny*inc1 + nz*inc2);
        float emno = acosf(fminf(fmaxf(dd, LO), HI));

        float* R = &sh[t * ROWSTRIDE];
        R[0] = v0x; R[1] = v0y; R[2] = v0z;
        R[3] = v1x; R[4] = v1y; R[5] = v1z;
        R[6] = v2x; R[7] = v2y; R[8] = v2z;
        R[9] = ang0; R[10] = ang1; R[11] = ang2;
        R[12] = nx; R[13] = ny; R[14] = nz;
        R[15] = area; R[16] = emno;
    }
    __syncthreads();

    // ---- Stage B: each thread emits its float4 column group for every face ----
    const int nf = min(TILE, F_ - fbase);
    float* ob = out + ((size_t)b * F_ + fbase) * (size_t)OUTC;
    for (int ff = 0; ff < nf; ff++) {
        const float* X = &sh[ff * ROWSTRIDE];
        float4 r = bias;
        if (seg == 0) {
            #pragma unroll
            for (int i = 0; i < 9; i++) {
                float x = X[i];
                r.x += x * w[4*i];   r.y += x * w[4*i+1];
                r.z += x * w[4*i+2]; r.w += x * w[4*i+3];
            }
        } else if (seg == 1) {
            #pragma unroll
            for (int i = 0; i < 3; i++) {
                float x = X[9 + i];
                r.x += x * w[4*i];   r.y += x * w[4*i+1];
                r.z += x * w[4*i+2]; r.w += x * w[4*i+3];
            }
        } else if (seg == 2) {
            #pragma unroll
            for (int i = 0; i < 3; i++) {
                float x = X[12 + i];
                r.x += x * w[4*i];   r.y += x * w[4*i+1];
                r.z += x * w[4*i+2]; r.w += x * w[4*i+3];
            }
        } else if (seg == 3) {
            float x = X[15];
            r.x += x * w[0]; r.y += x * w[1]; r.z += x * w[2]; r.w += x * w[3];
        }
        // seg == 4: r stays = bias (per-batch constant e_emangle)
        *(float4*)&ob[(size_t)ff * OUTC + c0] = r;

        if (t < 8) {
            float4 r2 = bias2;
            if (t < 4) {
                float x = X[16];
                r2.x += x * w2x; r2.y += x * w2y; r2.z += x * w2z; r2.w += x * w2w;
            }
            *(float4*)&ob[(size_t)ff * OUTC + 1024 + 4*t] = r2;
        }
    }
}

extern "C" void kernel_launch(void* const* d_in, const int* in_sizes, int n_in,
                              void* d_out, int out_size) {
    const float* vertices    = (const float*)d_in[0];
    const int*   faces       = (const int*)  d_in[1];
    const float* theta       = (const float*)d_in[2];
    const float* phi         = (const float*)d_in[3];
    const float* freq        = (const float*)d_in[4];
    const float* W_angle     = (const float*)d_in[5];
    const float* b_angle     = (const float*)d_in[6];
    const float* W_area      = (const float*)d_in[7];
    const float* b_area      = (const float*)d_in[8];
    const float* W_normal    = (const float*)d_in[9];
    const float* b_normal    = (const float*)d_in[10];
    const float* W_emnoangle = (const float*)d_in[11];
    const float* b_emnoangle = (const float*)d_in[12];
    const float* W_emangle   = (const float*)d_in[13];
    const float* b_emangle   = (const float*)d_in[14];
    const float* W_emfreq    = (const float*)d_in[15];
    const float* b_emfreq    = (const float*)d_in[16];
    const float* W_coor      = (const float*)d_in[17];
    const float* b_coor      = (const float*)d_in[18];

    mc_precompute<<<1, 256>>>(theta, phi, freq, W_emangle, b_emangle, W_emfreq, b_emfreq);

    dim3 grid((F_ + TILE - 1) / TILE, B_);
    mc_encode<<<grid, TPB>>>(vertices, faces,
                             W_angle, b_angle,
                             W_area, b_area,
                             W_normal, b_normal,
                             W_emnoangle, b_emnoangle,
                             W_coor, b_coor,
                             (float*)d_out);
}

// round 6
// speedup vs baseline: 1.5472x; 1.5472x over previous
#include <cuda_runtime.h>
#include <math.h>

// Problem constants (fixed by the dataset)
#define B_   8
#define V_   25000
#define F_   20000
#define TPB  256
#define TILE 256
#define ROWF 36            // floats per smem row (17 scalars duplicated + pad), 144B = 16B-aligned
#define OUTC 1056

typedef unsigned long long u64;

#define FMA2(d, a, bb, c) asm("fma.rn.f32x2 %0, %1, %2, %3;" : "=l"(d) : "l"(a), "l"(bb), "l"(c))

__device__ __forceinline__ u64 pack2(float lo, float hi) {
    u64 r; asm("mov.b64 %0, {%1,%2};" : "=l"(r) : "f"(lo), "f"(hi)); return r;
}

// Per-batch precomputed data (allocation-free scratch)
__device__ float g_incn[B_][4];       // normalized incidence vector
__device__ float g_emangle[B_][192];  // e_emangle = inc @ W_emangle + b (per-batch const)
__device__ float g_emfreq[B_][16];    // e_emfreq  = freq_log * W_emfreq + b (per-batch const)

__global__ void mc_precompute(const float* __restrict__ theta,
                              const float* __restrict__ phi,
                              const float* __restrict__ freq,
                              const float* __restrict__ W_emangle,
                              const float* __restrict__ b_emangle,
                              const float* __restrict__ W_emfreq,
                              const float* __restrict__ b_emfreq) {
    const float D2R = 0.017453292519943295f;
    int tid = threadIdx.x;
    if (tid < B_) {
        float th = theta[tid] * D2R, ph = phi[tid] * D2R;
        float ix = sinf(ph) * cosf(th);
        float iy = sinf(ph) * sinf(th);
        float iz = cosf(ph);
        float n  = sqrtf(ix*ix + iy*iy + iz*iz);
        float inv = 1.0f / fmaxf(n, 1e-12f);
        g_incn[tid][0] = ix * inv;
        g_incn[tid][1] = iy * inv;
        g_incn[tid][2] = iz * inv;
        g_incn[tid][3] = 0.0f;
    }
    for (int idx = tid; idx < B_ * 208; idx += blockDim.x) {
        int b = idx / 208, r = idx % 208;
        float th = theta[b] * D2R, ph = phi[b] * D2R;
        float ix = sinf(ph) * cosf(th);
        float iy = sinf(ph) * sinf(th);
        float iz = cosf(ph);
        if (r < 192) {
            g_emangle[b][r] = ix * W_emangle[r]
                            + iy * W_emangle[192 + r]
                            + iz * W_emangle[384 + r]
                            + b_emangle[r];
        } else {
            int j = r - 192;
            float fl = (log10f(freq[b]) + 1.0f) * 0.5f;
            g_emfreq[b][j] = fl * W_emfreq[j] + b_emfreq[j];
        }
    }
}

// Column segments of the 1056-wide output (thread t owns cols 4t..4t+3):
//   seg0 [0,576)     e_coor       t in [0,144)
//   seg1 [576,624)   e_angle      t in [144,156)
//   seg2 [624,816)   e_normal     t in [156,204)
//   seg3 [816,832)   e_area       t in [204,208)
//   seg4 [832,1024)  e_emangle    t in [208,256)   (per-batch const)
//   tail [1024,1040) e_emnoangle  handled by t in [224,228)
//   tail [1040,1056) e_emfreq     handled by t in [228,232)  (const)
//
// Smem row layout (duplicated pairs, float index):
//   0:v0x v0x  2:v0y v0y  4:v0z v0z  6:v1x v1x  8:v1y v1y 10:v1z v1z
//  12:v2x v2x 14:v2y v2y 16:v2z v2z 18:a0 a0 20:a1 a1 22:a2 a2
//  24:nx nx 26:ny ny 28:nz nz 30:area area 32:emno emno 34:pad pad
__global__ void __launch_bounds__(TPB, 3)
mc_encode(const float* __restrict__ vertices,
          const int*   __restrict__ faces,
          const float* __restrict__ W_angle,     const float* __restrict__ b_angle,
          const float* __restrict__ W_area,      const float* __restrict__ b_area,
          const float* __restrict__ W_normal,    const float* __restrict__ b_normal,
          const float* __restrict__ W_emnoangle, const float* __restrict__ b_emnoangle,
          const float* __restrict__ W_coor,      const float* __restrict__ b_coor,
          float* __restrict__ out) {
    __shared__ float sh[TILE * ROWF];
    const int t     = threadIdx.x;
    const int b     = blockIdx.y;
    const int fbase = blockIdx.x * TILE;
    const int c0    = 4 * t;

    const float inc0 = g_incn[b][0], inc1 = g_incn[b][1], inc2 = g_incn[b][2];

    // ---- Stage A: per-face geometry into shared memory (duplicated pairs) ----
    const int f = fbase + t;
    if (f < F_) {
        const int* fp = faces + ((size_t)b * F_ + f) * 3;
        int i0 = fp[0], i1 = fp[1], i2 = fp[2];
        const float* vb = vertices + (size_t)b * V_ * 3;
        float v0x = vb[3*i0], v0y = vb[3*i0+1], v0z = vb[3*i0+2];
        float v1x = vb[3*i1], v1y = vb[3*i1+1], v1z = vb[3*i1+2];
        float v2x = vb[3*i2], v2y = vb[3*i2+1], v2z = vb[3*i2+2];
        float e0x = v0x - v2x, e0y = v0y - v2y, e0z = v0z - v2z;
        float e1x = v1x - v0x, e1y = v1y - v0y, e1z = v1z - v0z;
        float e2x = v2x - v1x, e2y = v2y - v1y, e2z = v2z - v1z;
        float r0 = 1.0f / fmaxf(sqrtf(e0x*e0x + e0y*e0y + e0z*e0z), 1e-12f);
        float r1 = 1.0f / fmaxf(sqrtf(e1x*e1x + e1y*e1y + e1z*e1z), 1e-12f);
        float r2 = 1.0f / fmaxf(sqrtf(e2x*e2x + e2y*e2y + e2z*e2z), 1e-12f);
        float a0x = e0x*r0, a0y = e0y*r0, a0z = e0z*r0;
        float a1x = e1x*r1, a1y = e1y*r1, a1z = e1z*r1;
        float a2x = e2x*r2, a2y = e2y*r2, a2z = e2z*r2;
        const float LO = -1.0f + 1e-5f, HI = 1.0f - 1e-5f;
        float nd0 = -(a0x*a0z + a1x*a1z + a2x*a2z);
        float nd1 = -(a0y*a0x + a1y*a1x + a2y*a2x);
        float nd2 = -(a0z*a0y + a1z*a1y + a2z*a2y);
        float ang0 = acosf(fminf(fmaxf(nd0, LO), HI));
        float ang1 = acosf(fminf(fmaxf(nd1, LO), HI));
        float ang2 = acosf(fminf(fmaxf(nd2, LO), HI));
        float cx = e0y*e1z - e0z*e1y;
        float cy = e0z*e1x - e0x*e1z;
        float cz = e0x*e1y - e0y*e1x;
        float cn = sqrtf(cx*cx + cy*cy + cz*cz);
        float rc = 1.0f / fmaxf(cn, 1e-12f);
        float nx = cx*rc, ny = cy*rc, nz = cz*rc;
        float area = 0.5f * cn;
        float dd = -(nx*inc0 + ny*inc1 + nz*inc2);
        float emno = acosf(fminf(fmaxf(dd, LO), HI));

        float* R = &sh[t * ROWF];
        #define W2(k, v) *(float2*)&R[k] = make_float2((v), (v))
        W2(0,v0x);  W2(2,v0y);  W2(4,v0z);
        W2(6,v1x);  W2(8,v1y);  W2(10,v1z);
        W2(12,v2x); W2(14,v2y); W2(16,v2z);
        W2(18,ang0); W2(20,ang1); W2(22,ang2);
        W2(24,nx);  W2(26,ny);  W2(28,nz);
        W2(30,area); W2(32,emno);
        #undef W2
    }
    __syncthreads();

    // ---- Stage B: per-segment packed-FMA loops ----
    const int nf = min(TILE, F_ - fbase);
    float* op = out + ((size_t)b * F_ + fbase) * (size_t)OUTC + c0;
    const char* X = (const char*)sh;
    const long long ROWB = ROWF * 4;

    if (t < 144) {                                   // seg0: e_coor (9 inputs)
        u64 w01[9], w23[9];
        #pragma unroll
        for (int i = 0; i < 9; i++) {
            float4 wv = *(const float4*)&W_coor[i*576 + c0];
            w01[i] = pack2(wv.x, wv.y);
            w23[i] = pack2(wv.z, wv.w);
        }
        float4 bv = *(const float4*)&b_coor[c0];
        u64 b01 = pack2(bv.x, bv.y), b23 = pack2(bv.z, bv.w);
        #pragma unroll 2
        for (int ff = 0; ff < nf; ff++) {
            ulonglong2 q0 = *(const ulonglong2*)(X +  0);  // x0,x1
            ulonglong2 q1 = *(const ulonglong2*)(X + 16);  // x2,x3
            ulonglong2 q2 = *(const ulonglong2*)(X + 32);  // x4,x5
            ulonglong2 q3 = *(const ulonglong2*)(X + 48);  // x6,x7
            u64        q8 = *(const u64*)       (X + 64);  // x8
            u64 a01 = b01, a23 = b23;
            FMA2(a01, q0.x, w01[0], a01); FMA2(a23, q0.x, w23[0], a23);
            FMA2(a01, q0.y, w01[1], a01); FMA2(a23, q0.y, w23[1], a23);
            FMA2(a01, q1.x, w01[2], a01); FMA2(a23, q1.x, w23[2], a23);
            FMA2(a01, q1.y, w01[3], a01); FMA2(a23, q1.y, w23[3], a23);
            FMA2(a01, q2.x, w01[4], a01); FMA2(a23, q2.x, w23[4], a23);
            FMA2(a01, q2.y, w01[5], a01); FMA2(a23, q2.y, w23[5], a23);
            FMA2(a01, q3.x, w01[6], a01); FMA2(a23, q3.x, w23[6], a23);
            FMA2(a01, q3.y, w01[7], a01); FMA2(a23, q3.y, w23[7], a23);
            FMA2(a01, q8,   w01[8], a01); FMA2(a23, q8,   w23[8], a23);
            ulonglong2 st; st.x = a01; st.y = a23;
            *(ulonglong2*)op = st;
            op += OUTC; X += ROWB;
        }
    } else if (t < 156) {                            // seg1: e_angle (3 inputs)
        int j = c0 - 576;
        u64 w01[3], w23[3];
        #pragma unroll
        for (int i = 0; i < 3; i++) {
            float4 wv = *(const float4*)&W_angle[i*48 + j];
            w01[i] = pack2(wv.x, wv.y);
            w23[i] = pack2(wv.z, wv.w);
        }
        float4 bv = *(const float4*)&b_angle[j];
        u64 b01 = pack2(bv.x, bv.y), b23 = pack2(bv.z, bv.w);
        #pragma unroll 2
        for (int ff = 0; ff < nf; ff++) {
            u64        q0  = *(const u64*)       (X + 72);  // a0
            ulonglong2 q12 = *(const ulonglong2*)(X + 80);  // a1,a2
            u64 a01 = b01, a23 = b23;
            FMA2(a01, q0,    w01[0], a01); FMA2(a23, q0,    w23[0], a23);
            FMA2(a01, q12.x, w01[1], a01); FMA2(a23, q12.x, w23[1], a23);
            FMA2(a01, q12.y, w01[2], a01); FMA2(a23, q12.y, w23[2], a23);
            ulonglong2 st; st.x = a01; st.y = a23;
            *(ulonglong2*)op = st;
            op += OUTC; X += ROWB;
        }
    } else if (t < 204) {                            // seg2: e_normal (3 inputs)
        int j = c0 - 624;
        u64 w01[3], w23[3];
        #pragma unroll
        for (int i = 0; i < 3; i++) {
            float4 wv = *(const float4*)&W_normal[i*192 + j];
            w01[i] = pack2(wv.x, wv.y);
            w23[i] = pack2(wv.z, wv.w);
        }
        float4 bv = *(const float4*)&b_normal[j];
        u64 b01 = pack2(bv.x, bv.y), b23 = pack2(bv.z, bv.w);
        #pragma unroll 2
        for (int ff = 0; ff < nf; ff++) {
            ulonglong2 qxy = *(const ulonglong2*)(X +  96); // nx,ny
            u64        qz  = *(const u64*)       (X + 112); // nz
            u64 a01 = b01, a23 = b23;
            FMA2(a01, qxy.x, w01[0], a01); FMA2(a23, qxy.x, w23[0], a23);
            FMA2(a01, qxy.y, w01[1], a01); FMA2(a23, qxy.y, w23[1], a23);
            FMA2(a01, qz,    w01[2], a01); FMA2(a23, qz,    w23[2], a23);
            ulonglong2 st; st.x = a01; st.y = a23;
            *(ulonglong2*)op = st;
            op += OUTC; X += ROWB;
        }
    } else if (t < 208) {                            // seg3: e_area (1 input)
        int j = c0 - 816;
        float4 wv = *(const float4*)&W_area[j];
        float4 bv = *(const float4*)&b_area[j];
        u64 w01 = pack2(wv.x, wv.y), w23 = pack2(wv.z, wv.w);
        u64 b01 = pack2(bv.x, bv.y), b23 = pack2(bv.z, bv.w);
        #pragma unroll 2
        for (int ff = 0; ff < nf; ff++) {
            u64 qa = *(const u64*)(X + 120);                // area
            u64 a01 = b01, a23 = b23;
            FMA2(a01, qa, w01, a01); FMA2(a23, qa, w23, a23);
            ulonglong2 st; st.x = a01; st.y = a23;
            *(ulonglong2*)op = st;
            op += OUTC; X += ROWB;
        }
    } else {                                         // seg4: e_emangle const + tail cols
        int j = c0 - 832;
        float4 bv = *(const float4*)&g_emangle[b][j];
        ulonglong2 cst; cst.x = pack2(bv.x, bv.y); cst.y = pack2(bv.z, bv.w);

        // Tail columns 1024..1055 handled by threads 224..231 (warp 7)
        const bool tail_no = (t >= 224 && t < 228);  // e_emnoangle
        const bool tail_fr = (t >= 228 && t < 232);  // e_emfreq (const)
        u64 tw01 = 0, tw23 = 0;
        ulonglong2 tcst; tcst.x = 0; tcst.y = 0;
        float* op2 = out + ((size_t)b * F_ + fbase) * (size_t)OUTC + 1024;
        if (tail_no) {
            int jj = 4 * (t - 224);
            float4 wv = *(const float4*)&W_emnoangle[jj];
            float4 tb = *(const float4*)&b_emnoangle[jj];
            tw01 = pack2(wv.x, wv.y); tw23 = pack2(wv.z, wv.w);
            tcst.x = pack2(tb.x, tb.y); tcst.y = pack2(tb.z, tb.w);
            op2 += jj;
        } else if (tail_fr) {
            int jj = 4 * (t - 228);
            float4 tb = *(const float4*)&g_emfreq[b][jj];
            tcst.x = pack2(tb.x, tb.y); tcst.y = pack2(tb.z, tb.w);
            op2 += 16 + jj;
        }

        #pragma unroll 2
        for (int ff = 0; ff < nf; ff++) {
            *(ulonglong2*)op = cst;
            if (tail_no) {
                u64 q = *(const u64*)(X + 128);             // emno
                u64 a01 = tcst.x, a23 = tcst.y;
                FMA2(a01, q, tw01, a01); FMA2(a23, q, tw23, a23);
                ulonglong2 st; st.x = a01; st.y = a23;
                *(ulonglong2*)op2 = st;
            } else if (tail_fr) {
                *(ulonglong2*)op2 = tcst;
            }
            op += OUTC; op2 += OUTC; X += ROWB;
        }
    }
}

extern "C" void kernel_launch(void* const* d_in, const int* in_sizes, int n_in,
                              void* d_out, int out_size) {
    const float* vertices    = (const float*)d_in[0];
    const int*   faces       = (const int*)  d_in[1];
    const float* theta       = (const float*)d_in[2];
    const float* phi         = (const float*)d_in[3];
    const float* freq        = (const float*)d_in[4];
    const float* W_angle     = (const float*)d_in[5];
    const float* b_angle     = (const float*)d_in[6];
    const float* W_area      = (const float*)d_in[7];
    const float* b_area      = (const float*)d_in[8];
    const float* W_normal    = (const float*)d_in[9];
    const float* b_normal    = (const float*)d_in[10];
    const float* W_emnoangle = (const float*)d_in[11];
    const float* b_emnoangle = (const float*)d_in[12];
    const float* W_emangle   = (const float*)d_in[13];
    const float* b_emangle   = (const float*)d_in[14];
    const float* W_emfreq    = (const float*)d_in[15];
    const float* b_emfreq    = (const float*)d_in[16];
    const float* W_coor      = (const float*)d_in[17];
    const float* b_coor      = (const float*)d_in[18];

    mc_precompute<<<1, 256>>>(theta, phi, freq, W_emangle, b_emangle, W_emfreq, b_emfreq);

    dim3 grid((F_ + TILE - 1) / TILE, B_);
    mc_encode<<<grid, TPB>>>(vertices, faces,
                             W_angle, b_angle,
                             W_area, b_area,
                             W_normal, b_normal,
                             W_emnoangle, b_emnoangle,
                             W_coor, b_coor,
                             (float*)d_out);
}

// round 7
// speedup vs baseline: 1.8128x; 1.1717x over previous
#include <cuda_runtime.h>
#include <math.h>

// Problem constants (fixed by the dataset)
#define B_     8
#define V_     25000
#define F_     20000
#define TPB    256
#define TILE   160          // 125 tiles per batch exactly (20000 = 125*160)
#define ROWF   40           // floats per smem row = 160B, 16B-aligned sub-blocks
#define OUTC   1056

typedef unsigned long long u64;

#define FMA2(d, a, bb, c) asm("fma.rn.f32x2 %0, %1, %2, %3;" : "=l"(d) : "l"(a), "l"(bb), "l"(c))
#define STCS2(p, lo, hi)  asm volatile("st.global.cs.v2.u64 [%0], {%1,%2};" :: "l"(p), "l"(lo), "l"(hi) : "memory")

__device__ __forceinline__ u64 pack2(float lo, float hi) {
    u64 r; asm("mov.b64 %0, {%1,%2};" : "=l"(r) : "f"(lo), "f"(hi)); return r;
}

// Per-batch precomputed data (allocation-free scratch)
__device__ float g_incn[B_][4];
__device__ float g_emangle[B_][192];
__device__ float g_emfreq[B_][16];

__global__ void mc_precompute(const float* __restrict__ theta,
                              const float* __restrict__ phi,
                              const float* __restrict__ freq,
                              const float* __restrict__ W_emangle,
                              const float* __restrict__ b_emangle,
                              const float* __restrict__ W_emfreq,
                              const float* __restrict__ b_emfreq) {
    const float D2R = 0.017453292519943295f;
    int tid = threadIdx.x;
    if (tid < B_) {
        float th = theta[tid] * D2R, ph = phi[tid] * D2R;
        float ix = sinf(ph) * cosf(th);
        float iy = sinf(ph) * sinf(th);
        float iz = cosf(ph);
        float n  = sqrtf(ix*ix + iy*iy + iz*iz);
        float inv = 1.0f / fmaxf(n, 1e-12f);
        g_incn[tid][0] = ix * inv;
        g_incn[tid][1] = iy * inv;
        g_incn[tid][2] = iz * inv;
        g_incn[tid][3] = 0.0f;
    }
    for (int idx = tid; idx < B_ * 208; idx += blockDim.x) {
        int b = idx / 208, r = idx % 208;
        float th = theta[b] * D2R, ph = phi[b] * D2R;
        float ix = sinf(ph) * cosf(th);
        float iy = sinf(ph) * sinf(th);
        float iz = cosf(ph);
        if (r < 192) {
            g_emangle[b][r] = ix * W_emangle[r]
                            + iy * W_emangle[192 + r]
                            + iz * W_emangle[384 + r]
                            + b_emangle[r];
        } else {
            int j = r - 192;
            float fl = (log10f(freq[b]) + 1.0f) * 0.5f;
            g_emfreq[b][j] = fl * W_emfreq[j] + b_emfreq[j];
        }
    }
}

// Smem row layout (duplicated pairs, float index; 160B row, all reads in-row
// except the 8B tail read of the area/emno threads on the last row -> 8B pad):
//   [0..17]  x0..x8 (coor)      bytes   0..71
//   [18..19] pad0               bytes  72..79
//   [20..25] a0,a1,a2           bytes  80..103
//   [26..27] pad0               bytes 104..111
//   [28..33] nx,ny,nz           bytes 112..135
//   [34..35] pad0               bytes 136..143
//   [36..37] area               bytes 144..151
//   [38..39] emno               bytes 152..159
//
// Warp -> body (no intra-warp divergence):
//   w0-w3 : body9  coor cols [0,512)
//   w4    : body10 lane<16: coor [512,576) (o=0) | lane>=16: normal [624,688) (o=80, w slots 4,5,6)
//   w5    : body3  normal [688,816)          (o=112)
//   w6    : body3  lane<12 angle [576,624) (o=80) | lane<16 area [816,832) (o=144)
//                  | lane<20 emnoangle [1024,1040) (o=144) | lane<32 emangle-const [832,880) (o=80, w=0)
//   w7    : const  lane<28 emangle [880,992) | lane>=28 emfreq [1040,1056)
//                  + second store lane<8: emangle [992,1024)
__global__ void __launch_bounds__(TPB, 3)
mc_encode(const float* __restrict__ vertices,
          const int*   __restrict__ faces,
          const float* __restrict__ W_angle,     const float* __restrict__ b_angle,
          const float* __restrict__ W_area,      const float* __restrict__ b_area,
          const float* __restrict__ W_normal,    const float* __restrict__ b_normal,
          const float* __restrict__ W_emnoangle, const float* __restrict__ b_emnoangle,
          const float* __restrict__ W_coor,      const float* __restrict__ b_coor,
          float* __restrict__ out) {
    __shared__ float sh[TILE * ROWF + 4];   // +4 floats: zero pad past last row
    const int t     = threadIdx.x;
    const int w     = t >> 5;
    const int lane  = t & 31;
    const int b     = blockIdx.y;
    const int fbase = blockIdx.x * TILE;

    if (t < 4) sh[TILE * ROWF + t] = 0.0f;

    // ---- Stage A: per-face geometry into shared memory (t < TILE) ----
    if (t < TILE) {
        const float inc0 = g_incn[b][0], inc1 = g_incn[b][1], inc2 = g_incn[b][2];
        const int f = fbase + t;
        const int* fp = faces + ((size_t)b * F_ + f) * 3;
        int i0 = fp[0], i1 = fp[1], i2 = fp[2];
        const float* vb = vertices + (size_t)b * V_ * 3;
        float v0x = vb[3*i0], v0y = vb[3*i0+1], v0z = vb[3*i0+2];
        float v1x = vb[3*i1], v1y = vb[3*i1+1], v1z = vb[3*i1+2];
        float v2x = vb[3*i2], v2y = vb[3*i2+1], v2z = vb[3*i2+2];
        float e0x = v0x - v2x, e0y = v0y - v2y, e0z = v0z - v2z;
        float e1x = v1x - v0x, e1y = v1y - v0y, e1z = v1z - v0z;
        float e2x = v2x - v1x, e2y = v2y - v1y, e2z = v2z - v1z;
        float r0 = 1.0f / fmaxf(sqrtf(e0x*e0x + e0y*e0y + e0z*e0z), 1e-12f);
        float r1 = 1.0f / fmaxf(sqrtf(e1x*e1x + e1y*e1y + e1z*e1z), 1e-12f);
        float r2 = 1.0f / fmaxf(sqrtf(e2x*e2x + e2y*e2y + e2z*e2z), 1e-12f);
        float a0x = e0x*r0, a0y = e0y*r0, a0z = e0z*r0;
        float a1x = e1x*r1, a1y = e1y*r1, a1z = e1z*r1;
        float a2x = e2x*r2, a2y = e2y*r2, a2z = e2z*r2;
        const float LO = -1.0f + 1e-5f, HI = 1.0f - 1e-5f;
        float nd0 = -(a0x*a0z + a1x*a1z + a2x*a2z);
        float nd1 = -(a0y*a0x + a1y*a1x + a2y*a2x);
        float nd2 = -(a0z*a0y + a1z*a1y + a2z*a2y);
        float ang0 = acosf(fminf(fmaxf(nd0, LO), HI));
        float ang1 = acosf(fminf(fmaxf(nd1, LO), HI));
        float ang2 = acosf(fminf(fmaxf(nd2, LO), HI));
        float cx = e0y*e1z - e0z*e1y;
        float cy = e0z*e1x - e0x*e1z;
        float cz = e0x*e1y - e0y*e1x;
        float cn = sqrtf(cx*cx + cy*cy + cz*cz);
        float rc = 1.0f / fmaxf(cn, 1e-12f);
        float nx = cx*rc, ny = cy*rc, nz = cz*rc;
        float area = 0.5f * cn;
        float dd = -(nx*inc0 + ny*inc1 + nz*inc2);
        float emno = acosf(fminf(fmaxf(dd, LO), HI));

        float* R = &sh[t * ROWF];
        #define W2(k, v) *(float2*)&R[k] = make_float2((v), (v))
        W2(0,v0x);  W2(2,v0y);  W2(4,v0z);
        W2(6,v1x);  W2(8,v1y);  W2(10,v1z);
        W2(12,v2x); W2(14,v2y); W2(16,v2z);
        W2(18,0.0f);
        W2(20,ang0); W2(22,ang1); W2(24,ang2);
        W2(26,0.0f);
        W2(28,nx);  W2(30,ny);  W2(32,nz);
        W2(34,0.0f);
        W2(36,area); W2(38,emno);
        #undef W2
    }
    __syncthreads();

    // ---- Stage B: warp-uniform packed-FMA loops ----
    const char* X = (const char*)sh;
    const long long ROWB = ROWF * 4;
    float* const obase = out + ((size_t)b * F_ + fbase) * (size_t)OUTC;

    if (w < 4) {                                     // body9: pure coor, cols 4t
        const int c0 = 4 * t;
        u64 w01[9], w23[9];
        #pragma unroll
        for (int i = 0; i < 9; i++) {
            float4 wv = *(const float4*)&W_coor[i*576 + c0];
            w01[i] = pack2(wv.x, wv.y);
            w23[i] = pack2(wv.z, wv.w);
        }
        float4 bv = *(const float4*)&b_coor[c0];
        u64 b01 = pack2(bv.x, bv.y), b23 = pack2(bv.z, bv.w);
        float* op = obase + c0;
        #pragma unroll 2
        for (int ff = 0; ff < TILE; ff++) {
            ulonglong2 q0 = *(const ulonglong2*)(X +  0);
            ulonglong2 q1 = *(const ulonglong2*)(X + 16);
            ulonglong2 q2 = *(const ulonglong2*)(X + 32);
            ulonglong2 q3 = *(const ulonglong2*)(X + 48);
            u64        q8 = *(const u64*)       (X + 64);
            u64 a01 = b01, a23 = b23;
            FMA2(a01, q0.x, w01[0], a01); FMA2(a23, q0.x, w23[0], a23);
            FMA2(a01, q0.y, w01[1], a01); FMA2(a23, q0.y, w23[1], a23);
            FMA2(a01, q1.x, w01[2], a01); FMA2(a23, q1.x, w23[2], a23);
            FMA2(a01, q1.y, w01[3], a01); FMA2(a23, q1.y, w23[3], a23);
            FMA2(a01, q2.x, w01[4], a01); FMA2(a23, q2.x, w23[4], a23);
            FMA2(a01, q2.y, w01[5], a01); FMA2(a23, q2.y, w23[5], a23);
            FMA2(a01, q3.x, w01[6], a01); FMA2(a23, q3.x, w23[6], a23);
            FMA2(a01, q3.y, w01[7], a01); FMA2(a23, q3.y, w23[7], a23);
            FMA2(a01, q8,   w01[8], a01); FMA2(a23, q8,   w23[8], a23);
            STCS2(op, a01, a23);
            op += OUTC; X += ROWB;
        }
    } else if (w == 4) {                             // body10: generic 10-slot
        int o, c0;
        u64 w01[10], w23[10];
        #pragma unroll
        for (int i = 0; i < 10; i++) { w01[i] = 0; w23[i] = 0; }
        if (lane < 16) {                             // coor cols [512,576)
            o = 0; c0 = 512 + 4 * lane;
            #pragma unroll
            for (int i = 0; i < 9; i++) {
                float4 wv = *(const float4*)&W_coor[i*576 + c0];
                w01[i] = pack2(wv.x, wv.y);
                w23[i] = pack2(wv.z, wv.w);
            }
        } else {                                     // normal cols [624,688), slots 4,5,6
            o = 80; c0 = 624 + 4 * (lane - 16);
            int j = c0 - 624;
            #pragma unroll
            for (int i = 0; i < 3; i++) {
                float4 wv = *(const float4*)&W_normal[i*192 + j];
                w01[4+i] = pack2(wv.x, wv.y);
                w23[4+i] = pack2(wv.z, wv.w);
            }
        }
        float4 bv = (lane < 16) ? *(const float4*)&b_coor[c0]
                                : *(const float4*)&b_normal[c0 - 624];
        u64 b01 = pack2(bv.x, bv.y), b23 = pack2(bv.z, bv.w);
        float* op = obase + c0;
        const char* Xo = X + o;
        #pragma unroll 2
        for (int ff = 0; ff < TILE; ff++) {
            ulonglong2 q0 = *(const ulonglong2*)(Xo +  0);
            ulonglong2 q1 = *(const ulonglong2*)(Xo + 16);
            ulonglong2 q2 = *(const ulonglong2*)(Xo + 32);
            ulonglong2 q3 = *(const ulonglong2*)(Xo + 48);
            ulonglong2 q4 = *(const ulonglong2*)(Xo + 64);
            u64 a01 = b01, a23 = b23;
            FMA2(a01, q0.x, w01[0], a01); FMA2(a23, q0.x, w23[0], a23);
            FMA2(a01, q0.y, w01[1], a01); FMA2(a23, q0.y, w23[1], a23);
            FMA2(a01, q1.x, w01[2], a01); FMA2(a23, q1.x, w23[2], a23);
            FMA2(a01, q1.y, w01[3], a01); FMA2(a23, q1.y, w23[3], a23);
            FMA2(a01, q2.x, w01[4], a01); FMA2(a23, q2.x, w23[4], a23);
            FMA2(a01, q2.y, w01[5], a01); FMA2(a23, q2.y, w23[5], a23);
            FMA2(a01, q3.x, w01[6], a01); FMA2(a23, q3.x, w23[6], a23);
            FMA2(a01, q3.y, w01[7], a01); FMA2(a23, q3.y, w23[7], a23);
            FMA2(a01, q4.x, w01[8], a01); FMA2(a23, q4.x, w23[8], a23);
            FMA2(a01, q4.y, w01[9], a01); FMA2(a23, q4.y, w23[9], a23);
            STCS2(op, a01, a23);
            op += OUTC; Xo += ROWB;
        }
    } else if (w < 7) {                              // body3: generic 3-slot
        int o = 80, c0 = 0;
        u64 w01[3], w23[3];
        #pragma unroll
        for (int i = 0; i < 3; i++) { w01[i] = 0; w23[i] = 0; }
        u64 b01, b23;
        if (w == 5) {                                // normal cols [688,816)
            o = 112; c0 = 688 + 4 * lane;
            int j = c0 - 624;
            #pragma unroll
            for (int i = 0; i < 3; i++) {
                float4 wv = *(const float4*)&W_normal[i*192 + j];
                w01[i] = pack2(wv.x, wv.y);
                w23[i] = pack2(wv.z, wv.w);
            }
            float4 bv = *(const float4*)&b_normal[j];
            b01 = pack2(bv.x, bv.y); b23 = pack2(bv.z, bv.w);
        } else if (lane < 12) {                      // angle cols [576,624)
            o = 80; c0 = 576 + 4 * lane;
            int j = c0 - 576;
            #pragma unroll
            for (int i = 0; i < 3; i++) {
                float4 wv = *(const float4*)&W_angle[i*48 + j];
                w01[i] = pack2(wv.x, wv.y);
                w23[i] = pack2(wv.z, wv.w);
            }
            float4 bv = *(const float4*)&b_angle[j];
            b01 = pack2(bv.x, bv.y); b23 = pack2(bv.z, bv.w);
        } else if (lane < 16) {                      // area cols [816,832): slot0
            o = 144; c0 = 816 + 4 * (lane - 12);
            int j = c0 - 816;
            float4 wv = *(const float4*)&W_area[j];
            w01[0] = pack2(wv.x, wv.y); w23[0] = pack2(wv.z, wv.w);
            float4 bv = *(const float4*)&b_area[j];
            b01 = pack2(bv.x, bv.y); b23 = pack2(bv.z, bv.w);
        } else if (lane < 20) {                      // emnoangle cols [1024,1040): slot1
            o = 144; c0 = 1024 + 4 * (lane - 16);
            int j = c0 - 1024;
            float4 wv = *(const float4*)&W_emnoangle[j];
            w01[1] = pack2(wv.x, wv.y); w23[1] = pack2(wv.z, wv.w);
            float4 bv = *(const float4*)&b_emnoangle[j];
            b01 = pack2(bv.x, bv.y); b23 = pack2(bv.z, bv.w);
        } else {                                     // emangle const cols [832,880)
            o = 80; c0 = 832 + 4 * (lane - 20);
            float4 bv = *(const float4*)&g_emangle[b][c0 - 832];
            b01 = pack2(bv.x, bv.y); b23 = pack2(bv.z, bv.w);
        }
        float* op = obase + c0;
        const char* Xo = X + o;
        #pragma unroll 2
        for (int ff = 0; ff < TILE; ff++) {
            ulonglong2 q01 = *(const ulonglong2*)(Xo + 0);
            u64        q2  = *(const u64*)       (Xo + 16);
            u64 a01 = b01, a23 = b23;
            FMA2(a01, q01.x, w01[0], a01); FMA2(a23, q01.x, w23[0], a23);
            FMA2(a01, q01.y, w01[1], a01); FMA2(a23, q01.y, w23[1], a23);
            FMA2(a01, q2,    w01[2], a01); FMA2(a23, q2,    w23[2], a23);
            STCS2(op, a01, a23);
            op += OUTC; Xo += ROWB;
        }
    } else {                                         // w == 7: pure const
        int c0 = (lane < 28) ? (880 + 4 * lane) : (1040 + 4 * (lane - 28));
        float4 bv = (lane < 28) ? *(const float4*)&g_emangle[b][c0 - 832]
                                : *(const float4*)&g_emfreq[b][c0 - 1040];
        u64 c01 = pack2(bv.x, bv.y), c23 = pack2(bv.z, bv.w);
        const bool two = (lane < 8);
        int c1 = 992 + 4 * lane;                     // second group: emangle [992,1024)
        float4 bv2 = *(const float4*)&g_emangle[b][(two ? c1 : 992) - 832];
        u64 d01 = pack2(bv2.x, bv2.y), d23 = pack2(bv2.z, bv2.w);
        float* op  = obase + c0;
        float* op2 = obase + c1;
        #pragma unroll 2
        for (int ff = 0; ff < TILE; ff++) {
            STCS2(op, c01, c23);
            if (two) STCS2(op2, d01, d23);
            op += OUTC; op2 += OUTC;
        }
    }
}

extern "C" void kernel_launch(void* const* d_in, const int* in_sizes, int n_in,
                              void* d_out, int out_size) {
    const float* vertices    = (const float*)d_in[0];
    const int*   faces       = (const int*)  d_in[1];
    const float* theta       = (const float*)d_in[2];
    const float* phi         = (const float*)d_in[3];
    const float* freq        = (const float*)d_in[4];
    const float* W_angle     = (const float*)d_in[5];
    const float* b_angle     = (const float*)d_in[6];
    const float* W_area      = (const float*)d_in[7];
    const float* b_area      = (const float*)d_in[8];
    const float* W_normal    = (const float*)d_in[9];
    const float* b_normal    = (const float*)d_in[10];
    const float* W_emnoangle = (const float*)d_in[11];
    const float* b_emnoangle = (const float*)d_in[12];
    const float* W_emangle   = (const float*)d_in[13];
    const float* b_emangle   = (const float*)d_in[14];
    const float* W_emfreq    = (const float*)d_in[15];
    const float* b_emfreq    = (const float*)d_in[16];
    const float* W_coor      = (const float*)d_in[17];
    const float* b_coor      = (const float*)d_in[18];

    mc_precompute<<<1, 256>>>(theta, phi, freq, W_emangle, b_emangle, W_emfreq, b_emfreq);

    dim3 grid(F_ / TILE, B_);   // 125 x 8, no partial tiles
    mc_encode<<<grid, TPB>>>(vertices, faces,
                             W_angle, b_angle,
                             W_area, b_area,
                             W_normal, b_normal,
                             W_emnoangle, b_emnoangle,
                             W_coor, b_coor,
                             (float*)d_out);
}